// round 1
// baseline (speedup 1.0000x reference)
#include <cuda_runtime.h>
#include <math.h>

#define BB 16
#define NN (1 << 20)
#define HB 65536
#define HARD 512
#define RANDN 512
#define ULEN (NN - HARD)        // 1048064
#define UCAP 8192
#define MAXSLOTS 1152
#define SLOTCAP 96

// ---------------- scratch (static __device__, no allocs) ----------------
__device__ unsigned int g_hist[BB * HB];
__device__ unsigned int g_S[BB * (HB + 1)];      // suffix CDF: S[b] = #neg with bucket >= b
__device__ unsigned int g_num_pos[BB];
__device__ float        g_pos_loss[BB];
__device__ unsigned int g_pos_bits[BB * (NN / 32)];
__device__ int          g_M[BB];
__device__ unsigned int g_numneg[BB];
__device__ unsigned int g_ucand_cnt[BB];
__device__ float2       g_ucand[BB * UCAP];      // (u, bitcast(index))
__device__ unsigned int g_ranks[BB * RANDN];
__device__ unsigned int g_nranks[BB];
__device__ int          g_slot[BB * HB];         // -1 none, -2 marked, >=0 slot id
__device__ unsigned int g_nslots[BB];
__device__ unsigned int g_slot_cnt[BB * MAXSLOTS];
__device__ float        g_slot_vals[BB * MAXSLOTS * SLOTCAP];

__device__ __forceinline__ int conf_bucket(float c) {
    int b = (int)(c * 65536.0f);
    b = b < 0 ? 0 : (b > HB - 1 ? HB - 1 : b);
    return b;
}

// find b such that S[b] > q >= S[b+1]  (requires S[0] > q)
__device__ __forceinline__ int find_bucket(const unsigned int* S, unsigned int q) {
    int lo = 0, hi = HB;
    while (hi - lo > 1) {
        int mid = (lo + hi) >> 1;
        if (S[mid] > q) lo = mid; else hi = mid;
    }
    return lo;
}

// ---------------- K1: init ----------------
__global__ void k_init() {
    int idx = blockIdx.x * blockDim.x + threadIdx.x;
    int stride = gridDim.x * blockDim.x;
    for (int i = idx; i < BB * HB; i += stride) { g_hist[i] = 0u; g_slot[i] = -1; }
    for (int i = idx; i < BB * MAXSLOTS; i += stride) g_slot_cnt[i] = 0u;
    if (idx < BB) {
        g_num_pos[idx] = 0u; g_pos_loss[idx] = 0.0f;
        g_ucand_cnt[idx] = 0u; g_nranks[idx] = 0u; g_nslots[idx] = 0u;
    }
}

// ---------------- K2: main pass (pos/conf) ----------------
__global__ void k_pass1(const unsigned int* __restrict__ pos, const float* __restrict__ conf) {
    int idx = blockIdx.x * 256 + threadIdx.x;   // grid covers BB*NN exactly
    int img = idx >> 20;
    unsigned int p = pos[idx];                  // nonzero for int32 1 or float32 1.0
    float c = conf[idx];
    unsigned int ball = __ballot_sync(0xffffffffu, p != 0u);
    if ((threadIdx.x & 31) == 0) g_pos_bits[idx >> 5] = ball;

    float pl = 0.0f;
    if (p != 0u) {
        pl = -fmaxf(logf(c), -100.0f);
    } else {
        atomicAdd(&g_hist[img * HB + conf_bucket(c)], 1u);
    }
    for (int o = 16; o; o >>= 1) pl += __shfl_down_sync(0xffffffffu, pl, o);
    int pc = __popc(ball);
    __shared__ float s_pl[8]; __shared__ int s_pc[8];
    int w = threadIdx.x >> 5;
    if ((threadIdx.x & 31) == 0) { s_pl[w] = pl; s_pc[w] = pc; }
    __syncthreads();
    if (threadIdx.x == 0) {
        float t = 0.0f; int tc = 0;
        for (int i = 0; i < 8; i++) { t += s_pl[i]; tc += s_pc[i]; }
        atomicAdd(&g_pos_loss[img], t);
        atomicAdd(&g_num_pos[img], (unsigned int)tc);
    }
}

// ---------------- K3: suffix CDF per image ----------------
__global__ void k_scan() {
    int img = blockIdx.x;
    int t = threadIdx.x;                         // 256 threads, 256 buckets each
    const unsigned int* h = &g_hist[img * HB];
    unsigned int* S = &g_S[img * (HB + 1)];
    __shared__ unsigned int chunk[256];
    __shared__ unsigned int suf[257];
    unsigned int s = 0;
    for (int i = 0; i < 256; i++) s += h[t * 256 + i];
    chunk[t] = s;
    __syncthreads();
    if (t == 0) {
        suf[256] = 0;
        for (int i = 255; i >= 0; i--) suf[i] = suf[i + 1] + chunk[i];
    }
    __syncthreads();
    unsigned int run = suf[t + 1];
    for (int i = 255; i >= 0; i--) {
        int b = t * 256 + i;
        run += h[b];
        S[b] = run;
    }
    if (t == 0) {
        S[HB] = 0;
        unsigned int nn = suf[0];
        g_numneg[img] = nn;
        g_M[img] = (int)nn - HARD;
    }
}

// ---------------- K4: filter small u among i < M ----------------
__global__ void k_ufilter(const float* __restrict__ u) {
    long long idx = (long long)blockIdx.x * 256 + threadIdx.x;
    if (idx >= (long long)BB * ULEN) return;
    int img = (int)(idx / ULEN);
    int i = (int)(idx - (long long)img * ULEN);
    int M = g_M[img];
    if (i >= M) return;
    float uv = u[idx];
    float th = (M <= 4096) ? 2.0f : (1280.0f / (float)M);
    if (uv < th) {
        unsigned int p = atomicAdd(&g_ucand_cnt[img], 1u);
        if (p < UCAP) g_ucand[img * UCAP + p] = make_float2(uv, __int_as_float(i));
    }
}

// ---------------- K5: exact 512-smallest (u, idx) selection ----------------
__global__ void k_select() {
    int img = blockIdx.x >> 5;                   // 32 blocks/image
    int t = (blockIdx.x & 31) * 256 + threadIdx.x;
    unsigned int cnt = g_ucand_cnt[img];
    if (cnt > UCAP) cnt = UCAP;
    if ((unsigned int)t >= cnt) return;
    const float2* base = &g_ucand[img * UCAP];
    float2 me = base[t];
    float mu = me.x; int mi = __float_as_int(me.y);
    int r = 0;
    for (unsigned int j = 0; j < cnt; j++) {
        float2 o = base[j];
        int oi = __float_as_int(o.y);
        r += (o.x < mu) || (o.x == mu && oi < mi);
    }
    if (r < RANDN) {
        unsigned int p = atomicAdd(&g_nranks[img], 1u);
        g_ranks[img * RANDN + p] = (unsigned int)(HARD + mi);
    }
}

// ---------------- K6a: mark needed buckets ----------------
__global__ void k_mark() {
    int img = blockIdx.x;
    const unsigned int* S = &g_S[img * (HB + 1)];
    unsigned int nn = g_numneg[img];
    int HC = nn < HARD ? (int)nn : HARD;
    int nr = (int)g_nranks[img];
    int total = HC + nr;
    for (int qi = threadIdx.x; qi < total; qi += blockDim.x) {
        unsigned int q = (qi < HC) ? (unsigned int)qi : g_ranks[img * RANDN + (qi - HC)];
        int b = find_bucket(S, q);
        g_slot[img * HB + b] = -2;
    }
}

// ---------------- K6b: compact slot ids ----------------
__global__ void k_compact() {
    int idx = blockIdx.x * 256 + threadIdx.x;    // covers BB*HB exactly
    int img = idx >> 16;
    if (g_slot[idx] == -2) g_slot[idx] = (int)atomicAdd(&g_nslots[img], 1u);
}

// ---------------- K8: collect elements of needed buckets ----------------
__global__ void k_collect(const float* __restrict__ conf) {
    int idx = blockIdx.x * 256 + threadIdx.x;    // covers BB*NN exactly
    int img = idx >> 20;
    unsigned int bits = g_pos_bits[idx >> 5];
    if ((bits >> (idx & 31)) & 1u) return;       // positive -> skip
    float c = conf[idx];
    int b = conf_bucket(c);
    int s = g_slot[img * HB + b];
    if (s >= 0) {
        unsigned int p = atomicAdd(&g_slot_cnt[img * MAXSLOTS + s], 1u);
        if (p < SLOTCAP) g_slot_vals[(img * MAXSLOTS + s) * SLOTCAP + p] = c;
    }
}

// ---------------- K9: rank queries + final reduction ----------------
__global__ void k_final(float* __restrict__ out) {
    int img = blockIdx.x;
    const unsigned int* S = &g_S[img * (HB + 1)];
    unsigned int nn = g_numneg[img];
    int HC = nn < HARD ? (int)nn : HARD;
    int nr = (int)g_nranks[img];
    int total = HC + nr;
    float hard = 0.0f, rnd = 0.0f;
    for (int qi = threadIdx.x; qi < total; qi += blockDim.x) {
        bool isHard = qi < HC;
        unsigned int q = isHard ? (unsigned int)qi : g_ranks[img * RANDN + (qi - HC)];
        int b = find_bucket(S, q);
        unsigned int j = q - S[b + 1];           // descending rank within bucket
        int s = g_slot[img * HB + b];
        unsigned int c = g_slot_cnt[img * MAXSLOTS + s];
        if (c > SLOTCAP) c = SLOTCAP;
        const float* V = &g_slot_vals[(img * MAXSLOTS + s) * SLOTCAP];
        float v = 0.5f;
        for (unsigned int k = 0; k < c; k++) {
            float x = V[k];
            unsigned int g = 0, e = 0;
            for (unsigned int l = 0; l < c; l++) { float y = V[l]; g += (y > x); e += (y == x); }
            if (g <= j && j < g + e) { v = x; break; }
        }
        float term = -fmaxf(logf(1.0f - v), -100.0f);
        if (isHard) hard += term; else rnd += term;
    }
    for (int o = 16; o; o >>= 1) {
        hard += __shfl_down_sync(0xffffffffu, hard, o);
        rnd  += __shfl_down_sync(0xffffffffu, rnd, o);
    }
    __shared__ float sh[8], sr[8];
    int w = threadIdx.x >> 5;
    if ((threadIdx.x & 31) == 0) { sh[w] = hard; sr[w] = rnd; }
    __syncthreads();
    if (threadIdx.x == 0) {
        float H = 0.0f, R = 0.0f;
        for (int i = 0; i < 8; i++) { H += sh[i]; R += sr[i]; }
        float P = g_pos_loss[img];
        float outv;
        if (g_M[img] > 0) {
            outv = P + H + R;
        } else {
            float sn = (float)(g_num_pos[img] + (unsigned int)HC);
            outv = (P + H) / fmaxf(sn, 1.0f);
        }
        out[img] = outv;
    }
}

extern "C" void kernel_launch(void* const* d_in, const int* in_sizes, int n_in,
                              void* d_out, int out_size) {
    const unsigned int* pos = (const unsigned int*)d_in[0];
    const float* conf = (const float*)d_in[1];
    const float* u = (const float*)d_in[2];
    float* out = (float*)d_out;
    (void)in_sizes; (void)n_in; (void)out_size;

    k_init<<<2048, 256>>>();
    k_pass1<<<BB * NN / 256, 256>>>(pos, conf);
    k_scan<<<BB, 256>>>();
    k_ufilter<<<(BB * ULEN + 255) / 256, 256>>>(u);
    k_select<<<BB * 32, 256>>>();
    k_mark<<<BB, 256>>>();
    k_compact<<<BB * HB / 256, 256>>>();
    k_collect<<<BB * NN / 256, 256>>>(conf);
    k_final<<<BB, 256>>>(out);
}